// round 10
// baseline (speedup 1.0000x reference)
#include <cuda_runtime.h>

// TiDHy collapses algebraically: r stays zero through the scan, so
//   sl_rhat = sum_t mean_b sum_d (b_sd[d] - X[b,t,d])^2   (all T)
//   sl_rbar = same, t >= 1;  temp_loss = 0, r2_losses = 0, r0/r2 = zeros.
// One fused reduction over X (8 MB) + zero-fill of d_out.
//
// R10: tail deletion. Blocks accumulate the two scalars via float atomicAdd
// into device globals (overlapped with the CTA wave); the last arriving
// thread only loads 2 floats and stores 2 results. No last-block partial
// scan, no extra barriers after the release.

#define NB 256
#define NT 512

static constexpr int Bc  = 128;                 // batch
static constexpr int Tc  = 32;                  // timesteps
static constexpr int Dc  = 512;                 // input dim
static constexpr int NE4 = Bc * Tc * Dc / 4;    // 524288 float4
static constexpr int GSZ = NB * NT;             // 131072 threads; GSZ*4 == NE4

__device__ float g_acc_tot = 0.0f;   // sum over all (b,t,d)
__device__ float g_acc_tz  = 0.0f;   // t == 0 portion
__device__ int   g_counter = 0;

__global__ void __launch_bounds__(NT)
tidhy_fused_kernel(const float4* __restrict__ X4,
                   const float4* __restrict__ bsd4,
                   float* __restrict__ out, int out_size)
{
    const int tid  = threadIdx.x;
    const int bid  = blockIdx.x;
    const int gtid = bid * NT + tid;

    // Front-batched independent loads: MLP=4 (16 payload regs).
    float4 x0 = X4[gtid];
    float4 x1 = X4[gtid + GSZ];
    float4 x2 = X4[gtid + 2 * GSZ];
    float4 x3 = X4[gtid + 3 * GSZ];

    // GSZ is a multiple of 128 (=D/4) and 4096 (=D/4*T): d-index and
    // timestep are invariant across this thread's four loads.
    const float4 bs = __ldg(&bsd4[gtid & 127]);

    // Zero the output tuple. out[0..1] are overwritten by the finalizer,
    // whose store is happens-after every block's release (incl. this store).
    if (gtid < out_size) out[gtid] = 0.0f;

    float dx = x0.x - bs.x, dy = x0.y - bs.y, dz = x0.z - bs.z, dw = x0.w - bs.w;
    float s  = dx * dx + dy * dy + dz * dz + dw * dw;
    dx = x1.x - bs.x; dy = x1.y - bs.y; dz = x1.z - bs.z; dw = x1.w - bs.w;
    s += dx * dx + dy * dy + dz * dz + dw * dw;
    dx = x2.x - bs.x; dy = x2.y - bs.y; dz = x2.z - bs.z; dw = x2.w - bs.w;
    s += dx * dx + dy * dy + dz * dz + dw * dw;
    dx = x3.x - bs.x; dy = x3.y - bs.y; dz = x3.z - bs.z; dw = x3.w - bs.w;
    s += dx * dx + dy * dy + dz * dz + dw * dw;

    // Warp reduction of s only — t is identical across a warp's 32 lanes,
    // so the t==0 component falls out of the reduced value at the leader.
#pragma unroll
    for (int o = 16; o > 0; o >>= 1)
        s += __shfl_xor_sync(0xFFFFFFFFu, s, o);

    __shared__ float2 s_w[NT / 32];
    const int wid = tid >> 5;
    const int lid = tid & 31;
    if (lid == 0) {
        const bool is_t0 = (((gtid >> 7) & (Tc - 1)) == 0);
        s_w[wid] = make_float2(s, is_t0 ? s : 0.0f);
    }
    __syncthreads();

    if (wid == 0 && lid == 0) {
        float2 v = make_float2(0.0f, 0.0f);
#pragma unroll
        for (int w = 0; w < NT / 32; w++) { v.x += s_w[w].x; v.y += s_w[w].y; }

        // Per-block contribution into global accumulators (2 addresses,
        // 256 adds each: ~220 cyc L2-serialized, overlapped with the wave).
        atomicAdd(&g_acc_tot, v.x);
        atomicAdd(&g_acc_tz,  v.y);

        // Release-increment orders this block's atomics before the bump.
        int old;
        asm volatile("atom.release.gpu.global.add.s32 %0, [%1], 1;"
                     : "=r"(old) : "l"(&g_counter) : "memory");
        if (old == NB - 1) {
            // Last arriver finalizes: tiny tail, single thread.
            asm volatile("fence.acquire.gpu;" ::: "memory");
            float tot = g_acc_tot;
            float tzr = g_acc_tz;
            out[0] = tot / (float)Bc;           // sl_rhat (all t)
            out[1] = (tot - tzr) / (float)Bc;   // sl_rbar (t >= 1)
            // Reset for the next graph replay (next launch orders after us).
            g_acc_tot = 0.0f;
            g_acc_tz  = 0.0f;
            g_counter = 0;
        }
    }
}

extern "C" void kernel_launch(void* const* d_in, const int* in_sizes, int n_in,
                              void* d_out, int out_size)
{
    const float4* X4   = (const float4*)d_in[0];
    const float4* bsd4 = (const float4*)d_in[3];
    float* out = (float*)d_out;

    tidhy_fused_kernel<<<NB, NT>>>(X4, bsd4, out, out_size);
}

// round 12
// speedup vs baseline: 1.3429x; 1.3429x over previous
#include <cuda_runtime.h>

// TiDHy collapses algebraically: r stays zero through the scan, so
//   sl_rhat = sum_t mean_b sum_d (b_sd[d] - X[b,t,d])^2   (all T)
//   sl_rbar = same, t >= 1;  temp_loss = 0, r2_losses = 0, r0/r2 = zeros.
// One fused reduction over X (8 MB) + zero-fill of d_out.
//
// R11: revert R10's cross-replay-hazardous float atomics; restore the
// deterministic R9 structure (best: 8.67us, rel_err 0.0) with two cheaper
// serial leader sums replacing shuffle stages.

#define NB 256
#define NT 512

static constexpr int Bc  = 128;                 // batch
static constexpr int Tc  = 32;                  // timesteps
static constexpr int Dc  = 512;                 // input dim
static constexpr int NE4 = Bc * Tc * Dc / 4;    // 524288 float4
static constexpr int GSZ = NB * NT;             // 131072 threads; GSZ*4 == NE4

__device__ float2 g_partials[NB];
__device__ int    g_counter = 0;

__global__ void __launch_bounds__(NT)
tidhy_fused_kernel(const float4* __restrict__ X4,
                   const float4* __restrict__ bsd4,
                   float* __restrict__ out, int out_size)
{
    const int tid  = threadIdx.x;
    const int bid  = blockIdx.x;
    const int gtid = bid * NT + tid;

    // Front-batched independent loads: MLP=4 (16 payload regs).
    float4 x0 = X4[gtid];
    float4 x1 = X4[gtid + GSZ];
    float4 x2 = X4[gtid + 2 * GSZ];
    float4 x3 = X4[gtid + 3 * GSZ];

    // GSZ is a multiple of 128 (=D/4) and 4096 (=D/4*T): d-index and
    // timestep are invariant across this thread's four loads.
    const float4 bs = __ldg(&bsd4[gtid & 127]);

    // Zero the output tuple (out[0..1] overwritten by the last block below).
    if (gtid < out_size) out[gtid] = 0.0f;

    float dx = x0.x - bs.x, dy = x0.y - bs.y, dz = x0.z - bs.z, dw = x0.w - bs.w;
    float s  = dx * dx + dy * dy + dz * dz + dw * dw;
    dx = x1.x - bs.x; dy = x1.y - bs.y; dz = x1.z - bs.z; dw = x1.w - bs.w;
    s += dx * dx + dy * dy + dz * dz + dw * dw;
    dx = x2.x - bs.x; dy = x2.y - bs.y; dz = x2.z - bs.z; dw = x2.w - bs.w;
    s += dx * dx + dy * dy + dz * dz + dw * dw;
    dx = x3.x - bs.x; dy = x3.y - bs.y; dz = x3.z - bs.z; dw = x3.w - bs.w;
    s += dx * dx + dy * dy + dz * dz + dw * dw;

    // Warp reduction of s only — t is identical across a warp's 32 lanes,
    // so the t==0 component is derived at the leader.
#pragma unroll
    for (int o = 16; o > 0; o >>= 1)
        s += __shfl_xor_sync(0xFFFFFFFFu, s, o);

    __shared__ float2 s_w[NT / 32];
    __shared__ int    s_last;
    const int wid = tid >> 5;
    const int lid = tid & 31;
    if (lid == 0) {
        const bool is_t0 = (((gtid >> 7) & (Tc - 1)) == 0);
        s_w[wid] = make_float2(s, is_t0 ? s : 0.0f);
    }
    __syncthreads();

    if (tid == 0) {
        // Serial leader sum of 16 float2 slots (pipelined LDS, cheaper than
        // an 8-shuffle warp stage).
        float2 v = make_float2(0.0f, 0.0f);
#pragma unroll
        for (int w = 0; w < NT / 32; w++) { v.x += s_w[w].x; v.y += s_w[w].y; }
        g_partials[bid] = v;
        // Release-increment orders the partial store before the bump.
        int old;
        asm volatile("atom.release.gpu.global.add.s32 %0, [%1], 1;"
                     : "=r"(old) : "l"(&g_counter) : "memory");
        s_last = (old == NB - 1) ? 1 : 0;
    }
    __syncthreads();

    if (s_last) {
        // Last block: acquire pairs with the release adds; deterministic
        // reduction of NB=256 partials, one per thread, then serial finish.
        asm volatile("fence.acquire.gpu;" ::: "memory");
        float ft = 0.0f, f0 = 0.0f;
        if (tid < NB) {
            float2 pp = g_partials[tid];
            ft = pp.x;
            f0 = pp.y;
        }
#pragma unroll
        for (int o = 16; o > 0; o >>= 1) {
            ft += __shfl_xor_sync(0xFFFFFFFFu, ft, o);
            f0 += __shfl_xor_sync(0xFFFFFFFFu, f0, o);
        }
        if (lid == 0 && wid < NB / 32) s_w[wid] = make_float2(ft, f0);
        __syncthreads();
        if (tid == 0) {
            float tot = 0.0f, tzr = 0.0f;
#pragma unroll
            for (int w = 0; w < NB / 32; w++) { tot += s_w[w].x; tzr += s_w[w].y; }
            out[0] = tot / (float)Bc;           // sl_rhat (all t)
            out[1] = (tot - tzr) / (float)Bc;   // sl_rbar (t >= 1)
            g_counter = 0;                      // reset for next graph replay
        }
    }
}

extern "C" void kernel_launch(void* const* d_in, const int* in_sizes, int n_in,
                              void* d_out, int out_size)
{
    const float4* X4   = (const float4*)d_in[0];
    const float4* bsd4 = (const float4*)d_in[3];
    float* out = (float*)d_out;

    tidhy_fused_kernel<<<NB, NT>>>(X4, bsd4, out, out_size);
}

// round 13
// speedup vs baseline: 1.4574x; 1.0853x over previous
#include <cuda_runtime.h>

// TiDHy collapses algebraically: r stays zero through the scan, so
//   sl_rhat = sum_t mean_b sum_d (b_sd[d] - X[b,t,d])^2   (all T)
//   sl_rbar = same, t >= 1;  temp_loss = 0, r2_losses = 0, r0/r2 = zeros.
// One fused reduction over X (8 MB) + zero-fill of d_out.
//
// R13: tail confined to warp 0 — no second __syncthreads, no smem s_last
// broadcast, no post-reduce smem stage. Deterministic fixed-tree summation
// throughout (rel_err 0.0). Body is the proven R11 shape (256x512, U=4).

#define NB 256
#define NT 512

static constexpr int Bc  = 128;                 // batch
static constexpr int Tc  = 32;                  // timesteps
static constexpr int Dc  = 512;                 // input dim
static constexpr int NE4 = Bc * Tc * Dc / 4;    // 524288 float4
static constexpr int GSZ = NB * NT;             // 131072 threads; GSZ*4 == NE4

__device__ float2 g_partials[NB];
__device__ int    g_counter = 0;

__global__ void __launch_bounds__(NT)
tidhy_fused_kernel(const float4* __restrict__ X4,
                   const float4* __restrict__ bsd4,
                   float* __restrict__ out, int out_size)
{
    const int tid  = threadIdx.x;
    const int bid  = blockIdx.x;
    const int gtid = bid * NT + tid;

    // Front-batched independent loads: MLP=4 (16 payload regs).
    float4 x0 = X4[gtid];
    float4 x1 = X4[gtid + GSZ];
    float4 x2 = X4[gtid + 2 * GSZ];
    float4 x3 = X4[gtid + 3 * GSZ];

    // GSZ is a multiple of 128 (=D/4) and 4096 (=D/4*T): d-index and
    // timestep are invariant across this thread's four loads.
    const float4 bs = __ldg(&bsd4[gtid & 127]);

    // Zero the output tuple (out[0..1] overwritten by the finalizer below).
    if (gtid < out_size) out[gtid] = 0.0f;

    float dx = x0.x - bs.x, dy = x0.y - bs.y, dz = x0.z - bs.z, dw = x0.w - bs.w;
    float s  = dx * dx + dy * dy + dz * dz + dw * dw;
    dx = x1.x - bs.x; dy = x1.y - bs.y; dz = x1.z - bs.z; dw = x1.w - bs.w;
    s += dx * dx + dy * dy + dz * dz + dw * dw;
    dx = x2.x - bs.x; dy = x2.y - bs.y; dz = x2.z - bs.z; dw = x2.w - bs.w;
    s += dx * dx + dy * dy + dz * dz + dw * dw;
    dx = x3.x - bs.x; dy = x3.y - bs.y; dz = x3.z - bs.z; dw = x3.w - bs.w;
    s += dx * dx + dy * dy + dz * dz + dw * dw;

    // Warp reduction of s only — t is identical across a warp's 32 lanes,
    // so the t==0 component is derived at the leader.
#pragma unroll
    for (int o = 16; o > 0; o >>= 1)
        s += __shfl_xor_sync(0xFFFFFFFFu, s, o);

    __shared__ float2 s_w[NT / 32];
    const int wid = tid >> 5;
    const int lid = tid & 31;
    if (lid == 0) {
        const bool is_t0 = (((gtid >> 7) & (Tc - 1)) == 0);
        s_w[wid] = make_float2(s, is_t0 ? s : 0.0f);
    }
    __syncthreads();

    if (wid == 0) {
        int last = 0;
        if (lid == 0) {
            // Serial leader sum of 16 float2 smem slots (pipelined LDS).
            float2 v = make_float2(0.0f, 0.0f);
#pragma unroll
            for (int w = 0; w < NT / 32; w++) { v.x += s_w[w].x; v.y += s_w[w].y; }
            g_partials[bid] = v;
            // Release-increment orders the partial store before the bump.
            int old;
            asm volatile("atom.release.gpu.global.add.s32 %0, [%1], 1;"
                         : "=r"(old) : "l"(&g_counter) : "memory");
            last = (old == NB - 1) ? 1 : 0;
        }
        // Warp-local broadcast: no smem, no block barrier.
        last = __shfl_sync(0xFFFFFFFFu, last, 0);

        if (last) {
            // Final reduction entirely in warp 0 of the last-arriving block.
            asm volatile("fence.acquire.gpu;" ::: "memory");
            float ft = 0.0f, f0 = 0.0f;
#pragma unroll
            for (int k = 0; k < NB / 32; k++) {
                float2 pp = g_partials[k * 32 + lid];
                ft += pp.x;
                f0 += pp.y;
            }
#pragma unroll
            for (int o = 16; o > 0; o >>= 1) {
                ft += __shfl_xor_sync(0xFFFFFFFFu, ft, o);
                f0 += __shfl_xor_sync(0xFFFFFFFFu, f0, o);
            }
            if (lid == 0) {
                out[0] = ft / (float)Bc;          // sl_rhat (all t)
                out[1] = (ft - f0) / (float)Bc;   // sl_rbar (t >= 1)
                g_counter = 0;                    // reset for next graph replay
            }
        }
    }
}

extern "C" void kernel_launch(void* const* d_in, const int* in_sizes, int n_in,
                              void* d_out, int out_size)
{
    const float4* X4   = (const float4*)d_in[0];
    const float4* bsd4 = (const float4*)d_in[3];
    float* out = (float*)d_out;

    tidhy_fused_kernel<<<NB, NT>>>(X4, bsd4, out, out_size);
}